// round 15
// baseline (speedup 1.0000x reference)
#include <cuda_runtime.h>
#include <cuda_fp16.h>
#include <math.h>
#include <stdint.h>

// Problem constants
#define BB 4
#define SS 1024
#define DIM 2048
#define HH 32
#define HD 64
#define RR 16
#define MM (BB*SS)   // 4096

// ---------------- scratch (device globals; no allocation allowed) ----------------
__device__ __half g_whi[4][DIM*DIM];
__device__ __half g_xhi[MM*DIM];
__device__ float g_xq[MM*DIM];
__device__ __half g_xvh[MM*DIM];        // V projection, fp16, row layout
__device__ __half g_qh[MM*DIM];
__device__ __half g_ql[MM*DIM];
__device__ __half g_kh[MM*DIM];
__device__ __half g_vth[BB*HH*HD*SS];   // [bh][e][s] transposed V, fp16
__device__ float g_meml[BB*HH*HD*HD];
__device__ float g_memq[BB*HH*HD*HD];
__device__ float g_nrmt[BB*HH*HD];
__device__ float g_comb[MM*DIM];

__device__ __forceinline__ float elu1f(float x){ return x > 0.f ? x + 1.f : __expf(x); }
__device__ __forceinline__ float sigmf(float x){ return 1.f/(1.f+__expf(-x)); }

__device__ __forceinline__ uint32_t smem_u32(const void* p){
    uint32_t a;
    asm("{ .reg .u64 t; cvta.to.shared.u64 t, %1; cvt.u32.u64 %0, t; }" : "=r"(a) : "l"(p));
    return a;
}
__device__ __forceinline__ uint32_t pack2h(float x, float y){
    __half2 hh = __floats2half2_rn(x, y);
    return *(uint32_t*)&hh;
}

// ---------------- 1) fold LoRA + fp16 convert (fused x4, hi only) ----------------
struct FoldPtrs {
    const float* w[4];
    const float* l1[4];
    const float* l2[4];
};
__global__ __launch_bounds__(256)
void fold_split_all(FoldPtrs fp)
{
    int oi  = blockIdx.y;
    int row = blockIdx.x;
    int c0  = threadIdx.x * 8;
    const float* w  = fp.w[oi];
    const float* l1 = fp.l1[oi];
    const float* l2 = fp.l2[oi];
    float acc[8];
    const float4* wp = (const float4*)(w + (size_t)row*DIM + c0);
    float4 a = wp[0], b = wp[1];
    acc[0]=a.x; acc[1]=a.y; acc[2]=a.z; acc[3]=a.w;
    acc[4]=b.x; acc[5]=b.y; acc[6]=b.z; acc[7]=b.w;
#pragma unroll
    for (int r = 0; r < RR; r++){
        float s = __ldg(&l2[row*RR + r]);
        const float4* lp = (const float4*)(l1 + (size_t)r*DIM + c0);
        float4 u = lp[0], v = lp[1];
        acc[0]+=s*u.x; acc[1]+=s*u.y; acc[2]+=s*u.z; acc[3]+=s*u.w;
        acc[4]+=s*v.x; acc[5]+=s*v.y; acc[6]+=s*v.z; acc[7]+=s*v.w;
    }
    unsigned h[4];
#pragma unroll
    for (int p = 0; p < 4; p++){
        h[p] = (unsigned)__half_as_ushort(__float2half_rn(acc[2*p]))
             | ((unsigned)__half_as_ushort(__float2half_rn(acc[2*p+1])) << 16);
    }
    *(uint4*)(&g_whi[oi][(size_t)row*DIM + c0]) = make_uint4(h[0],h[1],h[2],h[3]);
}

// ---------------- 2) convert x to fp16 hi ----------------
__global__ __launch_bounds__(256)
void split_x_kernel(const float* __restrict__ src)
{
    size_t i = (size_t)(blockIdx.x*256 + threadIdx.x) * 8;
    const float4* p = (const float4*)(src + i);
    float4 a = p[0], b = p[1];
    unsigned h[4];
    h[0] = (unsigned)__half_as_ushort(__float2half_rn(a.x)) | ((unsigned)__half_as_ushort(__float2half_rn(a.y)) << 16);
    h[1] = (unsigned)__half_as_ushort(__float2half_rn(a.z)) | ((unsigned)__half_as_ushort(__float2half_rn(a.w)) << 16);
    h[2] = (unsigned)__half_as_ushort(__float2half_rn(b.x)) | ((unsigned)__half_as_ushort(__float2half_rn(b.y)) << 16);
    h[3] = (unsigned)__half_as_ushort(__float2half_rn(b.z)) | ((unsigned)__half_as_ushort(__float2half_rn(b.w)) << 16);
    *(uint4*)(&g_xhi[i]) = make_uint4(h[0], h[1], h[2], h[3]);
}

// ---------------- 3) HMMA GEMM (KC=32, 3-stage, 1-term); fused RoPE epilogue ----
#define KC 32
#define PITCH 40
#define SMAT (128*PITCH*2)            // 10240
#define OFF_AH 0
#define OFF_BH SMAT
#define STG_BYTES (2*SMAT)            // 20480
#define NSTG 3
#define NCH (DIM/KC)                  // 64

#define CP16(dst, src) asm volatile("cp.async.cg.shared.global [%0], [%1], 16;" :: "r"(dst), "l"(src))
#define CPCOMMIT()  asm volatile("cp.async.commit_group;" ::: "memory")
#define CPWAIT1()   asm volatile("cp.async.wait_group 1;" ::: "memory")
#define CPWAIT0()   asm volatile("cp.async.wait_group 0;" ::: "memory")
#define LDM4(r0,r1,r2,r3,addr) \
    asm volatile("ldmatrix.sync.aligned.m8n8.x4.shared.b16 {%0,%1,%2,%3}, [%4];" \
        : "=r"(r0), "=r"(r1), "=r"(r2), "=r"(r3) : "r"(addr))
#define MMA16816(c, a0,a1,a2,a3, b0,b1) \
    asm volatile("mma.sync.aligned.m16n8k16.row.col.f32.f16.f16.f32 " \
        "{%0,%1,%2,%3}, {%4,%5,%6,%7}, {%8,%9}, {%0,%1,%2,%3};" \
        : "+f"((c)[0]), "+f"((c)[1]), "+f"((c)[2]), "+f"((c)[3]) \
        : "r"(a0), "r"(a1), "r"(a2), "r"(a3), "r"(b0), "r"(b1))

// MODE 0: fused QKV with RoPE/fp16 epilogue; MODE 1: output projection (fp32 out)
template<int MODE>
__device__ __forceinline__ void gemm_body(float* Yext,
                                          const float* __restrict__ fc,
                                          const float* __restrict__ fs)
{
    extern __shared__ char dsm[];
    int t = threadIdx.x, lane = t & 31, wid = t >> 5;
    int wm = wid >> 2, wn = wid & 3;
    int m0 = blockIdx.y * 128;
    int n0g = blockIdx.x * 128;

    int widx, ncol;
    if (MODE == 0){
        widx = n0g >> 11;          // 0=Q, 1=K, 2=V
        ncol = n0g & 2047;
    } else {
        widx = 3; ncol = n0g;
    }
    const __half* Bhp = g_whi[widx] + (size_t)ncol*DIM;

    uint32_t sb0 = smem_u32(dsm);

    int pr = t >> 1, pc = (t & 1) * 16;
    const __half* gAh = g_xhi + (size_t)(m0 + pr)*DIM + pc;
    const __half* gBh = Bhp   + (size_t)pr*DIM + pc;
    uint32_t dA = sb0 + (uint32_t)((pr*PITCH + pc)*2);

    float acc[4][4][4];
#pragma unroll
    for (int i = 0; i < 4; i++)
#pragma unroll
        for (int j = 0; j < 4; j++)
#pragma unroll
            for (int k = 0; k < 4; k++) acc[i][j][k] = 0.f;

#pragma unroll
    for (int c = 0; c < 2; c++){
        uint32_t d = dA + c*STG_BYTES;
        int k0 = c*KC;
        CP16(d + OFF_AH, gAh + k0);  CP16(d + OFF_AH + 16, gAh + k0 + 8);
        CP16(d + OFF_BH, gBh + k0);  CP16(d + OFF_BH + 16, gBh + k0 + 8);
        CPCOMMIT();
    }

    int rsel = lane & 15;
    int csel = (lane >> 4) * 8;
    int stg = 0, pstg = 2;

#pragma unroll 1
    for (int ch = 0; ch < NCH; ch++){
        if (ch == NCH - 1) { CPWAIT0(); } else { CPWAIT1(); }
        __syncthreads();

        if (ch + 2 < NCH){
            uint32_t d = dA + pstg*STG_BYTES;
            int k0 = (ch + 2)*KC;
            CP16(d + OFF_AH, gAh + k0);  CP16(d + OFF_AH + 16, gAh + k0 + 8);
            CP16(d + OFF_BH, gBh + k0);  CP16(d + OFF_BH + 16, gBh + k0 + 8);
            CPCOMMIT();
            pstg = (pstg == 2) ? 0 : pstg + 1;
        }

        uint32_t base = sb0 + stg*STG_BYTES;
        stg = (stg == 2) ? 0 : stg + 1;
#pragma unroll
        for (int ks = 0; ks < 2; ks++){
            int kofs = ks*16 + csel;
            uint32_t Bh[8];
#pragma unroll
            for (int p = 0; p < 2; p++){
                uint32_t ab = base + OFF_BH + (uint32_t)(((wn*32 + p*16 + rsel)*PITCH + kofs)*2);
                uint32_t r0,r1,r2,r3;
                LDM4(r0,r1,r2,r3, ab);
                Bh[4*p+0]=r0; Bh[4*p+1]=r2; Bh[4*p+2]=r1; Bh[4*p+3]=r3;
            }
#pragma unroll
            for (int mt = 0; mt < 4; mt++){
                uint32_t aa = base + OFF_AH + (uint32_t)(((wm*64 + mt*16 + rsel)*PITCH + kofs)*2);
                uint32_t a0,a1,a2,a3;
                LDM4(a0,a1,a2,a3, aa);
#pragma unroll
                for (int nt = 0; nt < 4; nt++){
                    int p = nt >> 1, o = nt & 1;
                    MMA16816(acc[mt][nt], a0,a1,a2,a3, Bh[4*p + 2*o], Bh[4*p + 2*o + 1]);
                }
            }
        }
    }

    // ---------------- epilogue ----------------
    int grp = lane >> 2, tig = lane & 3;
#pragma unroll
    for (int mt = 0; mt < 4; mt++){
        int r0 = m0 + wm*64 + mt*16 + grp;
        int s0r = r0 & (SS-1);
        int s1r = (r0 + 8) & (SS-1);
#pragma unroll
        for (int nt = 0; nt < 4; nt++){
            int c = ncol + wn*32 + nt*8 + tig*2;
            float a0 = acc[mt][nt][0], b0 = acc[mt][nt][1];
            float a1 = acc[mt][nt][2], b1 = acc[mt][nt][3];
            if (MODE == 1){
                *(float2*)&Yext[(size_t)r0*DIM + c]     = make_float2(a0, b0);
                *(float2*)&Yext[(size_t)(r0+8)*DIM + c] = make_float2(a1, b1);
            } else if (widx == 2){
                *(uint32_t*)&g_xvh[(size_t)r0*DIM + c]     = pack2h(a0, b0);
                *(uint32_t*)&g_xvh[(size_t)(r0+8)*DIM + c] = pack2h(a1, b1);
            } else {
                int i = (c & 63) >> 1;
                float c0 = __ldg(&fc[s0r*32 + i]), sn0 = __ldg(&fs[s0r*32 + i]);
                float c1 = __ldg(&fc[s1r*32 + i]), sn1 = __ldg(&fs[s1r*32 + i]);
                float ra0 = a0*c0 - b0*sn0, rb0 = a0*sn0 + b0*c0;
                float ra1 = a1*c1 - b1*sn1, rb1 = a1*sn1 + b1*c1;
                if (widx == 1){
                    *(uint32_t*)&g_kh[(size_t)r0*DIM + c]     = pack2h(ra0, rb0);
                    *(uint32_t*)&g_kh[(size_t)(r0+8)*DIM + c] = pack2h(ra1, rb1);
                } else {
                    *(float2*)&g_xq[(size_t)r0*DIM + c]     = make_float2(a0, b0);
                    *(float2*)&g_xq[(size_t)(r0+8)*DIM + c] = make_float2(a1, b1);
                    ra0 *= 0.125f; rb0 *= 0.125f; ra1 *= 0.125f; rb1 *= 0.125f;
                    __half h0 = __float2half_rn(ra0), h1 = __float2half_rn(rb0);
                    __half h2 = __float2half_rn(ra1), h3 = __float2half_rn(rb1);
                    *(uint32_t*)&g_qh[(size_t)r0*DIM + c] =
                        (uint32_t)__half_as_ushort(h0) | ((uint32_t)__half_as_ushort(h1) << 16);
                    *(uint32_t*)&g_qh[(size_t)(r0+8)*DIM + c] =
                        (uint32_t)__half_as_ushort(h2) | ((uint32_t)__half_as_ushort(h3) << 16);
                    *(uint32_t*)&g_ql[(size_t)r0*DIM + c] =
                        pack2h(ra0 - __half2float(h0), rb0 - __half2float(h1));
                    *(uint32_t*)&g_ql[(size_t)(r0+8)*DIM + c] =
                        pack2h(ra1 - __half2float(h2), rb1 - __half2float(h3));
                }
            }
        }
    }
}

__global__ __launch_bounds__(256, 2)
void gemm_qkv(const float* __restrict__ fc, const float* __restrict__ fs)
{ gemm_body<0>(nullptr, fc, fs); }

__global__ __launch_bounds__(256, 2)
void gemm_out(float* __restrict__ out) { gemm_body<1>(out, nullptr, nullptr); }

// ---------------- 4a) init memory buffers ----------------
__global__ __launch_bounds__(256)
void mem_init_kernel(const float* __restrict__ meml_in,
                     const float* __restrict__ memq_in,
                     const float* __restrict__ nrm_in)
{
    int i = blockIdx.x*256 + threadIdx.x;
    g_meml[i] = meml_in[i];
    g_memq[i] = memq_in[i];
    if (i < BB*HH*HD) g_nrmt[i] = nrm_in[i];
}

// ---------------- 4b) memory-branch statistics, chunked over seq ----------------
__global__ __launch_bounds__(256)
void mem_stats_kernel(const float* __restrict__ cache_k,
                      const float* __restrict__ cache_v,
                      const float* __restrict__ pquery)
{
    int bh = blockIdx.x;
    int sc = blockIdx.y;
    int b = bh >> 5, h = bh & 31;
    __shared__ float Ks[32][64];
    __shared__ float Vs[32][64];
    __shared__ float pqs[64];
    __shared__ float sig[32];

    int t = threadIdx.x;
    if (t < 64) pqs[t] = pquery[(b*HH + h)*HD + t];

    float accl[4][4] = {{0}}, accq[4][4] = {{0}};
    float accn = 0.f;
    int lrow = t >> 3;
    int lcol = (t & 7) * 8;
    int d0 = (t >> 4) * 4;
    int e0 = (t & 15) * 4;

    for (int s0 = sc*128; s0 < sc*128 + 128; s0 += 32) {
        __syncthreads();
        const float* kp = cache_k + ((size_t)((b*SS + s0 + lrow)*HH + h))*HD + lcol;
        const float* vp = cache_v + ((size_t)((b*SS + s0 + lrow)*HH + h))*HD + lcol;
        *(float4*)&Ks[lrow][lcol]   = *(const float4*)kp;
        *(float4*)&Ks[lrow][lcol+4] = *(const float4*)(kp + 4);
        *(float4*)&Vs[lrow][lcol]   = *(const float4*)vp;
        *(float4*)&Vs[lrow][lcol+4] = *(const float4*)(vp + 4);
        __syncthreads();
        if (t < 32) {
            float sum = 0.f;
#pragma unroll
            for (int d = 0; d < 64; d++) sum += pqs[d] * Ks[t][d];
            sig[t] = sigmf(sum * 0.125f);
        }
        __syncthreads();
#pragma unroll
        for (int u = 0; u < 8; u++) Ks[lrow][lcol+u] = elu1f(Ks[lrow][lcol+u]);
        __syncthreads();
        if (t < 64) {
#pragma unroll
            for (int s = 0; s < 32; s++) accn += Ks[s][t];
        }
#pragma unroll 4
        for (int s = 0; s < 32; s++) {
            float4 k4 = *(const float4*)&Ks[s][d0];
            float4 v4 = *(const float4*)&Vs[s][e0];
            float sg = sig[s];
            float ka[4] = {k4.x, k4.y, k4.z, k4.w};
            float kb[4] = {k4.x*sg, k4.y*sg, k4.z*sg, k4.w*sg};
            float vv[4] = {v4.x, v4.y, v4.z, v4.w};
#pragma unroll
            for (int i = 0; i < 4; i++)
#pragma unroll
                for (int j = 0; j < 4; j++) {
                    accl[i][j] += ka[i] * vv[j];
                    accq[i][j] += kb[i] * vv[j];
                }
        }
    }
    size_t base = (size_t)bh * HD * HD;
#pragma unroll
    for (int i = 0; i < 4; i++)
#pragma unroll
        for (int j = 0; j < 4; j++) {
            size_t idx = base + (size_t)(d0 + i)*HD + (e0 + j);
            atomicAdd(&g_meml[idx], accl[i][j]);
            atomicAdd(&g_memq[idx], accq[i][j]);
        }
    if (t < 64) atomicAdd(&g_nrmt[bh*HD + t], accn);
}

// ---------------- 5) memory-branch apply -> g_comb ----------------
__global__ __launch_bounds__(256)
void mem_apply_kernel(const float* __restrict__ gmem_w,
                      const float* __restrict__ gmem_b,
                      const float* __restrict__ gate)
{
    int idx = blockIdx.x;
    int st = idx & 31;
    int h  = (idx >> 5) & 31;
    int b  = idx >> 10;
    int bh = b*HH + h;
    int s0 = st * 32;

    __shared__ float ml[64*64];
    __shared__ float mq[64*64];
    __shared__ float sq[32*68];
    __shared__ float nrm[64];
    __shared__ float wv[64];
    __shared__ float gpart[32*8];

    int t = threadIdx.x;
    {
        int r = t >> 2, c = (t & 3) * 16;
        size_t gbase = (size_t)bh*HD*HD + (size_t)r*HD + c;
#pragma unroll
        for (int u = 0; u < 4; u++) {
            *(float4*)&ml[r*64 + c + 4*u] = *(const float4*)&g_meml[gbase + 4*u];
            *(float4*)&mq[r*64 + c + 4*u] = *(const float4*)&g_memq[gbase + 4*u];
        }
    }
    {
        int r = t >> 3, c = (t & 7) * 8;
        const float* xp = g_xq + ((size_t)((b*SS + s0 + r)*HH + h))*HD + c;
        float4 a = *(const float4*)xp;
        float4 bv = *(const float4*)(xp + 4);
        float4 ea = make_float4(elu1f(a.x), elu1f(a.y), elu1f(a.z), elu1f(a.w));
        float4 eb = make_float4(elu1f(bv.x), elu1f(bv.y), elu1f(bv.z), elu1f(bv.w));
        *(float4*)&sq[r*68 + c]     = ea;
        *(float4*)&sq[r*68 + c + 4] = eb;
    }
    if (t < 64) { nrm[t] = g_nrmt[bh*HD + t]; wv[t] = gmem_w[t]; }
    __syncthreads();

    int row = t >> 3;
    int eq  = t & 7;
    float denom = 0.f;
#pragma unroll
    for (int d = 0; d < 64; d++) denom += sq[row*68 + d] * nrm[d];

    float4 mo[2]  = {make_float4(0,0,0,0), make_float4(0,0,0,0)};
    float4 qmo[2] = {make_float4(0,0,0,0), make_float4(0,0,0,0)};
#pragma unroll
    for (int d = 0; d < 64; d++) {
        float sd = sq[row*68 + d];
#pragma unroll
        for (int c = 0; c < 2; c++) {
            float4 m4 = *(const float4*)&ml[d*64 + eq*4 + 32*c];
            float4 q4 = *(const float4*)&mq[d*64 + eq*4 + 32*c];
            mo[c].x += sd*m4.x; mo[c].y += sd*m4.y; mo[c].z += sd*m4.z; mo[c].w += sd*m4.w;
            qmo[c].x += sd*q4.x; qmo[c].y += sd*q4.y; qmo[c].z += sd*q4.z; qmo[c].w += sd*q4.w;
        }
    }
    float inv = 1.f / denom;
    float gp = 0.f;
#pragma unroll
    for (int c = 0; c < 2; c++) {
        mo[c].x *= inv; mo[c].y *= inv; mo[c].z *= inv; mo[c].w *= inv;
        qmo[c].x *= inv; qmo[c].y *= inv; qmo[c].z *= inv; qmo[c].w *= inv;
        int e = eq*4 + 32*c;
        gp += qmo[c].x*wv[e] + qmo[c].y*wv[e+1] + qmo[c].z*wv[e+2] + qmo[c].w*wv[e+3];
    }
    gpart[row*8 + eq] = gp;
    __syncthreads();
    float gsum = 0.f;
#pragma unroll
    for (int i = 0; i < 8; i++) gsum += gpart[row*8 + i];
    float gq = sigmf(gsum + gmem_b[0]);
    float gh = sigmf(gate[h]);

    float* op = g_comb + ((size_t)((b*SS + s0 + row)*HH + h))*HD;
#pragma unroll
    for (int c = 0; c < 2; c++) {
        float4 o;
        o.x = gh * (mo[c].x + gq*qmo[c].x);
        o.y = gh * (mo[c].y + gq*qmo[c].y);
        o.z = gh * (mo[c].z + gq*qmo[c].z);
        o.w = gh * (mo[c].w + gq*qmo[c].w);
        *(float4*)(op + eq*4 + 32*c) = o;
    }
}

// ---------------- 6) transpose V (fp16 in) -> g_vth fp16 ----------------
__global__ __launch_bounds__(256)
void v_trans_kernel()
{
    __shared__ __half sm[64*72];
    int bh = blockIdx.x & 127;
    int st = blockIdx.x >> 7;
    int b = bh >> 5, h = bh & 31;
    int s0 = st * 64;
    int t = threadIdx.x;

    {
        int sl = t >> 2, e0 = (t & 3) * 16;
        const __half* vp = g_xvh + ((size_t)((b*SS + s0 + sl)*HH + h))*HD + e0;
        uint4 v0 = *(const uint4*)vp;
        uint4 v1 = *(const uint4*)(vp + 8);
        *(uint4*)&sm[sl*72 + e0]     = v0;
        *(uint4*)&sm[sl*72 + e0 + 8] = v1;
    }
    __syncthreads();
    {
        int el = t >> 2, sb = (t & 3) * 16;
        __half hv[16];
#pragma unroll
        for (int j = 0; j < 16; j++) hv[j] = sm[(sb + j)*72 + el];
        __half* dst = g_vth + ((size_t)(bh*HD + el))*SS + s0 + sb;
        *(uint4*)dst       = *(uint4*)&hv[0];
        *(uint4*)(dst + 8) = *(uint4*)&hv[8];
    }
}

// ---------------- 7) HMMA flash attention, 128-row Q tiles ----------
#define PF 72
#define FQL (128*PF)                 // Q-lo offset (halves)
#define FST0 (2*128*PF)              // K/V stages start (halves)
#define FSTG (2*64*PF)               // per-stage stride (halves)

__device__ __forceinline__ void flash_load_kv(uint32_t skb, int t, int bh, int b, int h, int kt)
{
    int r = t >> 2, c0 = (t & 3) * 16;
    const __half* ks = g_kh + ((size_t)((b*SS + kt*64 + r)*HH + h))*HD + c0;
    const __half* vs = g_vth + ((size_t)(bh*HD + r))*SS + kt*64 + c0;
    uint32_t dk = skb + (uint32_t)((r*PF + c0)*2);
    uint32_t dv = dk + 64*PF*2;
    CP16(dk, ks); CP16(dk+16, ks+8);
    CP16(dv, vs); CP16(dv+16, vs+8);
}

__global__ __launch_bounds__(256)
void flash_mma(const float* __restrict__ gate)
{
    extern __shared__ __half fsm[];
    int t = threadIdx.x, lane = t & 31, wid = t >> 5;   // 8 warps
    int qt = blockIdx.x & 7;                            // 128-row q-tile
    int h  = (blockIdx.x >> 3) & 31;
    int b  = blockIdx.x >> 8;
    int bh = b*HH + h;
    uint32_t sb = smem_u32(fsm);

    {   // stage Q (128 rows, hi + lo)
        int r = t >> 1, c0 = (t & 1) * 32;
        const __half* qsh = g_qh + ((size_t)((b*SS + qt*128 + r)*HH + h))*HD + c0;
        const __half* qsl = g_ql + ((size_t)((b*SS + qt*128 + r)*HH + h))*HD + c0;
        uint32_t dh = sb + (uint32_t)((r*PF + c0)*2);
        uint32_t dl = dh + FQL*2;
        CP16(dh, qsh); CP16(dh+16, qsh+8); CP16(dh+32, qsh+16); CP16(dh+48, qsh+24);
        CP16(dl, qsl); CP16(dl+16, qsl+8); CP16(dl+32, qsl+16); CP16(dl+48, qsl+24);
        CPCOMMIT();
    }
    flash_load_kv(sb + FST0*2, t, bh, b, h, 0);
    CPCOMMIT();

    CPWAIT1();
    __syncthreads();
    int rsel = lane & 15, csel = (lane >> 4) * 8;
    uint32_t qh[4][4], ql[4][4];
#pragma unroll
    for (int ks = 0; ks < 4; ks++){
        uint32_t a = sb + (uint32_t)(((wid*16 + rsel)*PF + ks*16 + csel)*2);
        LDM4(qh[ks][0], qh[ks][1], qh[ks][2], qh[ks][3], a);
        LDM4(ql[ks][0], ql[ks][1], ql[ks][2], ql[ks][3], a + FQL*2);
    }

    float m0 = -1e30f, m1 = -1e30f, l0 = 0.f, l1 = 0.f;
    float O[8][4];
#pragma unroll
    for (int j = 0; j < 8; j++)
#pragma unroll
        for (int r = 0; r < 4; r++) O[j][r] = 0.f;

    int g  = lane >> 2, t2 = lane & 3;
    int NT = 2*qt + 2;

#pragma unroll 1
    for (int kt = 0; kt < NT; kt++){
        CPWAIT0();
        __syncthreads();
        if (kt + 1 < NT){
            flash_load_kv(sb + (FST0 + ((kt+1)&1)*FSTG)*2, t, bh, b, h, kt+1);
            CPCOMMIT();
        }
        uint32_t kbase = sb + (uint32_t)((FST0 + (kt&1)*FSTG)*2);
        uint32_t vbase = kbase + 64*PF*2;

        float sacc[8][4];
#pragma unroll
        for (int j = 0; j < 8; j++)
#pragma unroll
            for (int r = 0; r < 4; r++) sacc[j][r] = 0.f;
#pragma unroll
        for (int ks = 0; ks < 4; ks++){
#pragma unroll
            for (int nb = 0; nb < 4; nb++){
                uint32_t r0,r1,r2,r3;
                LDM4(r0,r1,r2,r3, kbase + (uint32_t)(((nb*16 + rsel)*PF + ks*16 + csel)*2));
                MMA16816(sacc[2*nb],   qh[ks][0],qh[ks][1],qh[ks][2],qh[ks][3], r0, r2);
                MMA16816(sacc[2*nb],   ql[ks][0],ql[ks][1],ql[ks][2],ql[ks][3], r0, r2);
                MMA16816(sacc[2*nb+1], qh[ks][0],qh[ks][1],qh[ks][2],qh[ks][3], r1, r3);
                MMA16816(sacc[2*nb+1], ql[ks][0],ql[ks][1],ql[ks][2],ql[ks][3], r1, r3);
            }
        }
        if (kt >= 2*qt){
            // causal mask within the trailing tiles: local row (within q-tile)
            // vs column offset of this k-tile
            int rl0 = wid*16 + g - (kt - 2*qt)*64;     // row-limit for rows 0..
            int rl1 = rl0 + 8;
#pragma unroll
            for (int j = 0; j < 8; j++){
                int n0 = j*8 + t2*2, n1 = n0 + 1;
                if (n0 > rl0) sacc[j][0] = -1e30f;
                if (n1 > rl0) sacc[j][1] = -1e30f;
                if (n0 > rl1) sacc[j][2] = -1e30f;
                if (n1 > rl1) sacc[j][3] = -1e30f;
            }
        }
        float vx0 = -1e30f, vx1 = -1e30f;
#pragma unroll
        for (int j = 0; j < 8; j++){
            vx0 = fmaxf(vx0, fmaxf(sacc[j][0], sacc[j][1]));
            vx1 = fmaxf(vx1, fmaxf(sacc[j][2], sacc[j][3]));
        }
        vx0 = fmaxf(vx0, __shfl_xor_sync(0xffffffffu, vx0, 1));
        vx0 = fmaxf(vx0, __shfl_xor_sync(0xffffffffu, vx0, 2));
        vx1 = fmaxf(vx1, __shfl_xor_sync(0xffffffffu, vx1, 1));
        vx1 = fmaxf(vx1, __shfl_xor_sync(0xffffffffu, vx1, 2));
        float n0f = fmaxf(m0, vx0), n1f = fmaxf(m1, vx1);
        float c0f = __expf(m0 - n0f), c1f = __expf(m1 - n1f);
        m0 = n0f; m1 = n1f;
        float s0 = 0.f, s1 = 0.f;
#pragma unroll
        for (int j = 0; j < 8; j++){
            sacc[j][0] = __expf(sacc[j][0] - n0f);
            sacc[j][1] = __expf(sacc[j][1] - n0f);
            sacc[j][2] = __expf(sacc[j][2] - n1f);
            sacc[j][3] = __expf(sacc[j][3] - n1f);
            s0 += sacc[j][0] + sacc[j][1];
            s1 += sacc[j][2] + sacc[j][3];
        }
        s0 += __shfl_xor_sync(0xffffffffu, s0, 1);
        s0 += __shfl_xor_sync(0xffffffffu, s0, 2);
        s1 += __shfl_xor_sync(0xffffffffu, s1, 1);
        s1 += __shfl_xor_sync(0xffffffffu, s1, 2);
        l0 = l0*c0f + s0;
        l1 = l1*c1f + s1;
#pragma unroll
        for (int j = 0; j < 8; j++){
            O[j][0] *= c0f; O[j][1] *= c0f;
            O[j][2] *= c1f; O[j][3] *= c1f;
        }
        uint32_t pa[4][4];
#pragma unroll
        for (int ks = 0; ks < 4; ks++){
            pa[ks][0] = pack2h(sacc[2*ks][0],   sacc[2*ks][1]);
            pa[ks][1] = pack2h(sacc[2*ks][2],   sacc[2*ks][3]);
            pa[ks][2] = pack2h(sacc[2*ks+1][0], sacc[2*ks+1][1]);
            pa[ks][3] = pack2h(sacc[2*ks+1][2], sacc[2*ks+1][3]);
        }
#pragma unroll
        for (int ks = 0; ks < 4; ks++){
#pragma unroll
            for (int nb = 0; nb < 4; nb++){
                uint32_t r0,r1,r2,r3;
                LDM4(r0,r1,r2,r3, vbase + (uint32_t)(((nb*16 + rsel)*PF + ks*16 + csel)*2));
                MMA16816(O[2*nb],   pa[ks][0],pa[ks][1],pa[ks][2],pa[ks][3], r0, r2);
                MMA16816(O[2*nb+1], pa[ks][0],pa[ks][1],pa[ks][2],pa[ks][3], r1, r3);
            }
        }
    }

    float gh_ = sigmf(gate[h]);
    float w0 = (1.f - gh_) / l0;
    float w1 = (1.f - gh_) / l1;
    size_t row0 = ((size_t)((b*SS + qt*128 + wid*16 + g)*HH + h))*HD;
    size_t row1 = row0 + (size_t)8*HH*HD;
#pragma unroll
    for (int j = 0; j < 8; j++){
        int c = j*8 + t2*2;
        float2 p0 = *(float2*)&g_comb[row0 + c];
        *(uint32_t*)&g_xhi[row0 + c] = pack2h(p0.x + w0*O[j][0], p0.y + w0*O[j][1]);
        float2 p1 = *(float2*)&g_comb[row1 + c];
        *(uint32_t*)&g_xhi[row1 + c] = pack2h(p1.x + w1*O[j][2], p1.y + w1*O[j][3]);
    }
}

// ---------------- launcher ----------------
extern "C" void kernel_launch(void* const* d_in, const int* in_sizes, int n_in,
                              void* d_out, int out_size)
{
    const float* x     = (const float*)d_in[0];
    const float* pq    = (const float*)d_in[1];
    const float* ck    = (const float*)d_in[2];
    const float* cv    = (const float*)d_in[3];
    const float* meml  = (const float*)d_in[4];
    const float* memq  = (const float*)d_in[5];
    const float* nrm   = (const float*)d_in[6];
    const float* fc    = (const float*)d_in[7];
    const float* fs    = (const float*)d_in[8];
    const float* wq    = (const float*)d_in[10];
    const float* wk    = (const float*)d_in[11];
    const float* wv    = (const float*)d_in[12];
    const float* wo    = (const float*)d_in[13];
    const float* lq1   = (const float*)d_in[14];
    const float* lq2   = (const float*)d_in[15];
    const float* lk1   = (const float*)d_in[16];
    const float* lk2   = (const float*)d_in[17];
    const float* lv1   = (const float*)d_in[18];
    const float* lv2   = (const float*)d_in[19];
    const float* lo1   = (const float*)d_in[20];
    const float* lo2   = (const float*)d_in[21];
    const float* gate  = (const float*)d_in[22];
    const float* gw    = (const float*)d_in[23];
    const float* gb    = (const float*)d_in[24];
    float* out = (float*)d_out;

    static cudaStream_t s2 = nullptr, s3 = nullptr;
    static cudaEvent_t evFork = nullptr, evMem = nullptr, evG = nullptr,
                       evV = nullptr, evW = nullptr;
    if (!s2){
        cudaStreamCreateWithFlags(&s2, cudaStreamNonBlocking);
        cudaStreamCreateWithFlags(&s3, cudaStreamNonBlocking);
        cudaEventCreateWithFlags(&evFork, cudaEventDisableTiming);
        cudaEventCreateWithFlags(&evMem,  cudaEventDisableTiming);
        cudaEventCreateWithFlags(&evG,    cudaEventDisableTiming);
        cudaEventCreateWithFlags(&evV,    cudaEventDisableTiming);
        cudaEventCreateWithFlags(&evW,    cudaEventDisableTiming);
    }

    size_t gsm = NSTG * STG_BYTES;
    cudaFuncSetAttribute(gemm_qkv, cudaFuncAttributeMaxDynamicSharedMemorySize, (int)gsm);
    cudaFuncSetAttribute(gemm_out, cudaFuncAttributeMaxDynamicSharedMemorySize, (int)gsm);
    size_t fsmem = (size_t)(2*128*PF + 2*2*64*PF) * sizeof(__half);   // 73728 B
    cudaFuncSetAttribute(flash_mma, cudaFuncAttributeMaxDynamicSharedMemorySize, (int)fsmem);

    cudaEventRecord(evFork, 0);

    // side branch s2: memory-branch statistics (hidden under QKV GEMM)
    cudaStreamWaitEvent(s2, evFork, 0);
    mem_init_kernel<<<(BB*HH*HD*HD)/256, 256, 0, s2>>>(meml, memq, nrm);
    mem_stats_kernel<<<dim3(BB*HH, 8), 256, 0, s2>>>(ck, cv, pq);
    cudaEventRecord(evMem, s2);

    // side branch s3: weight fold runs concurrently with x conversion
    FoldPtrs fp;
    fp.w[0] = wq; fp.w[1] = wk; fp.w[2] = wv; fp.w[3] = wo;
    fp.l1[0] = lq1; fp.l1[1] = lk1; fp.l1[2] = lv1; fp.l1[3] = lo1;
    fp.l2[0] = lq2; fp.l2[1] = lk2; fp.l2[2] = lv2; fp.l2[3] = lo2;
    cudaStreamWaitEvent(s3, evFork, 0);
    fold_split_all<<<dim3(DIM, 4), 256, 0, s3>>>(fp);
    cudaEventRecord(evW, s3);

    // main: x convert + fused QKV GEMM (RoPE epilogue)
    split_x_kernel<<<(MM*DIM)/(256*8), 256>>>(x);
    cudaStreamWaitEvent(0, evW, 0);
    gemm_qkv<<<dim3(3*DIM/128, MM/128), 256, gsm>>>(fc, fs);
    cudaEventRecord(evG, 0);

    // post-GEMM: v_trans on side stream, mem_apply on main
    cudaStreamWaitEvent(s3, evG, 0);
    v_trans_kernel<<<BB*HH*(SS/64), 256, 0, s3>>>();
    cudaEventRecord(evV, s3);

    cudaStreamWaitEvent(0, evMem, 0);
    mem_apply_kernel<<<BB*HH*(SS/32), 256>>>(gw, gb, gate);

    // join, flash (128-row q-tiles), output projection
    cudaStreamWaitEvent(0, evV, 0);
    flash_mma<<<BB*HH*(SS/128), 256, fsmem>>>(gate);
    gemm_out<<<dim3(DIM/128, MM/128), 256, gsm>>>(out);
    (void)in_sizes; (void)n_in; (void)out_size;
}

// round 16
// speedup vs baseline: 1.6462x; 1.6462x over previous
#include <cuda_runtime.h>
#include <cuda_fp16.h>
#include <math.h>
#include <stdint.h>

// Problem constants
#define BB 4
#define SS 1024
#define DIM 2048
#define HH 32
#define HD 64
#define RR 16
#define MM (BB*SS)   // 4096

// ---------------- scratch (device globals; no allocation allowed) ----------------
__device__ __half g_whi[4][DIM*DIM];
__device__ __half g_xhi[MM*DIM];
__device__ float g_xq[MM*DIM];
__device__ __half g_xvh[MM*DIM];        // V projection, fp16, row layout
__device__ __half g_qh[MM*DIM];
__device__ __half g_kh[MM*DIM];
__device__ __half g_vth[BB*HH*HD*SS];   // [bh][e][s] transposed V, fp16
__device__ float g_meml[BB*HH*HD*HD];
__device__ float g_memq[BB*HH*HD*HD];
__device__ float g_nrmt[BB*HH*HD];
__device__ float g_comb[MM*DIM];

__device__ __forceinline__ float elu1f(float x){ return x > 0.f ? x + 1.f : __expf(x); }
__device__ __forceinline__ float sigmf(float x){ return 1.f/(1.f+__expf(-x)); }

__device__ __forceinline__ uint32_t smem_u32(const void* p){
    uint32_t a;
    asm("{ .reg .u64 t; cvta.to.shared.u64 t, %1; cvt.u32.u64 %0, t; }" : "=r"(a) : "l"(p));
    return a;
}
__device__ __forceinline__ uint32_t pack2h(float x, float y){
    __half2 hh = __floats2half2_rn(x, y);
    return *(uint32_t*)&hh;
}

// ---------------- 1) fold LoRA + fp16 convert (fused x4, hi only) ----------------
struct FoldPtrs {
    const float* w[4];
    const float* l1[4];
    const float* l2[4];
};
__global__ __launch_bounds__(256)
void fold_split_all(FoldPtrs fp)
{
    int oi  = blockIdx.y;
    int row = blockIdx.x;
    int c0  = threadIdx.x * 8;
    const float* w  = fp.w[oi];
    const float* l1 = fp.l1[oi];
    const float* l2 = fp.l2[oi];
    float acc[8];
    const float4* wp = (const float4*)(w + (size_t)row*DIM + c0);
    float4 a = wp[0], b = wp[1];
    acc[0]=a.x; acc[1]=a.y; acc[2]=a.z; acc[3]=a.w;
    acc[4]=b.x; acc[5]=b.y; acc[6]=b.z; acc[7]=b.w;
#pragma unroll
    for (int r = 0; r < RR; r++){
        float s = __ldg(&l2[row*RR + r]);
        const float4* lp = (const float4*)(l1 + (size_t)r*DIM + c0);
        float4 u = lp[0], v = lp[1];
        acc[0]+=s*u.x; acc[1]+=s*u.y; acc[2]+=s*u.z; acc[3]+=s*u.w;
        acc[4]+=s*v.x; acc[5]+=s*v.y; acc[6]+=s*v.z; acc[7]+=s*v.w;
    }
    unsigned h[4];
#pragma unroll
    for (int p = 0; p < 4; p++){
        h[p] = (unsigned)__half_as_ushort(__float2half_rn(acc[2*p]))
             | ((unsigned)__half_as_ushort(__float2half_rn(acc[2*p+1])) << 16);
    }
    *(uint4*)(&g_whi[oi][(size_t)row*DIM + c0]) = make_uint4(h[0],h[1],h[2],h[3]);
}

// ---------------- 2) convert x to fp16 hi ----------------
__global__ __launch_bounds__(256)
void split_x_kernel(const float* __restrict__ src)
{
    size_t i = (size_t)(blockIdx.x*256 + threadIdx.x) * 8;
    const float4* p = (const float4*)(src + i);
    float4 a = p[0], b = p[1];
    unsigned h[4];
    h[0] = (unsigned)__half_as_ushort(__float2half_rn(a.x)) | ((unsigned)__half_as_ushort(__float2half_rn(a.y)) << 16);
    h[1] = (unsigned)__half_as_ushort(__float2half_rn(a.z)) | ((unsigned)__half_as_ushort(__float2half_rn(a.w)) << 16);
    h[2] = (unsigned)__half_as_ushort(__float2half_rn(b.x)) | ((unsigned)__half_as_ushort(__float2half_rn(b.y)) << 16);
    h[3] = (unsigned)__half_as_ushort(__float2half_rn(b.z)) | ((unsigned)__half_as_ushort(__float2half_rn(b.w)) << 16);
    *(uint4*)(&g_xhi[i]) = make_uint4(h[0], h[1], h[2], h[3]);
}

// ---------------- 3) HMMA GEMM (KC=32, 3-stage, 1-term); fused RoPE epilogue ----
#define KC 32
#define PITCH 40
#define SMAT (128*PITCH*2)            // 10240
#define OFF_AH 0
#define OFF_BH SMAT
#define STG_BYTES (2*SMAT)            // 20480
#define NSTG 3
#define NCH (DIM/KC)                  // 64

#define CP16(dst, src) asm volatile("cp.async.cg.shared.global [%0], [%1], 16;" :: "r"(dst), "l"(src))
#define CPCOMMIT()  asm volatile("cp.async.commit_group;" ::: "memory")
#define CPWAIT1()   asm volatile("cp.async.wait_group 1;" ::: "memory")
#define CPWAIT0()   asm volatile("cp.async.wait_group 0;" ::: "memory")
#define LDM4(r0,r1,r2,r3,addr) \
    asm volatile("ldmatrix.sync.aligned.m8n8.x4.shared.b16 {%0,%1,%2,%3}, [%4];" \
        : "=r"(r0), "=r"(r1), "=r"(r2), "=r"(r3) : "r"(addr))
#define MMA16816(c, a0,a1,a2,a3, b0,b1) \
    asm volatile("mma.sync.aligned.m16n8k16.row.col.f32.f16.f16.f32 " \
        "{%0,%1,%2,%3}, {%4,%5,%6,%7}, {%8,%9}, {%0,%1,%2,%3};" \
        : "+f"((c)[0]), "+f"((c)[1]), "+f"((c)[2]), "+f"((c)[3]) \
        : "r"(a0), "r"(a1), "r"(a2), "r"(a3), "r"(b0), "r"(b1))

// MODE 0: fused QKV with RoPE/fp16 epilogue; MODE 1: output projection (fp32 out)
template<int MODE>
__device__ __forceinline__ void gemm_body(float* Yext,
                                          const float* __restrict__ fc,
                                          const float* __restrict__ fs)
{
    extern __shared__ char dsm[];
    int t = threadIdx.x, lane = t & 31, wid = t >> 5;
    int wm = wid >> 2, wn = wid & 3;
    int m0 = blockIdx.y * 128;
    int n0g = blockIdx.x * 128;

    int widx, ncol;
    if (MODE == 0){
        widx = n0g >> 11;          // 0=Q, 1=K, 2=V
        ncol = n0g & 2047;
    } else {
        widx = 3; ncol = n0g;
    }
    const __half* Bhp = g_whi[widx] + (size_t)ncol*DIM;

    uint32_t sb0 = smem_u32(dsm);

    int pr = t >> 1, pc = (t & 1) * 16;
    const __half* gAh = g_xhi + (size_t)(m0 + pr)*DIM + pc;
    const __half* gBh = Bhp   + (size_t)pr*DIM + pc;
    uint32_t dA = sb0 + (uint32_t)((pr*PITCH + pc)*2);

    float acc[4][4][4];
#pragma unroll
    for (int i = 0; i < 4; i++)
#pragma unroll
        for (int j = 0; j < 4; j++)
#pragma unroll
            for (int k = 0; k < 4; k++) acc[i][j][k] = 0.f;

#pragma unroll
    for (int c = 0; c < 2; c++){
        uint32_t d = dA + c*STG_BYTES;
        int k0 = c*KC;
        CP16(d + OFF_AH, gAh + k0);  CP16(d + OFF_AH + 16, gAh + k0 + 8);
        CP16(d + OFF_BH, gBh + k0);  CP16(d + OFF_BH + 16, gBh + k0 + 8);
        CPCOMMIT();
    }

    int rsel = lane & 15;
    int csel = (lane >> 4) * 8;
    int stg = 0, pstg = 2;

#pragma unroll 1
    for (int ch = 0; ch < NCH; ch++){
        if (ch == NCH - 1) { CPWAIT0(); } else { CPWAIT1(); }
        __syncthreads();

        if (ch + 2 < NCH){
            uint32_t d = dA + pstg*STG_BYTES;
            int k0 = (ch + 2)*KC;
            CP16(d + OFF_AH, gAh + k0);  CP16(d + OFF_AH + 16, gAh + k0 + 8);
            CP16(d + OFF_BH, gBh + k0);  CP16(d + OFF_BH + 16, gBh + k0 + 8);
            CPCOMMIT();
            pstg = (pstg == 2) ? 0 : pstg + 1;
        }

        uint32_t base = sb0 + stg*STG_BYTES;
        stg = (stg == 2) ? 0 : stg + 1;
#pragma unroll
        for (int ks = 0; ks < 2; ks++){
            int kofs = ks*16 + csel;
            uint32_t Bh[8];
#pragma unroll
            for (int p = 0; p < 2; p++){
                uint32_t ab = base + OFF_BH + (uint32_t)(((wn*32 + p*16 + rsel)*PITCH + kofs)*2);
                uint32_t r0,r1,r2,r3;
                LDM4(r0,r1,r2,r3, ab);
                Bh[4*p+0]=r0; Bh[4*p+1]=r2; Bh[4*p+2]=r1; Bh[4*p+3]=r3;
            }
#pragma unroll
            for (int mt = 0; mt < 4; mt++){
                uint32_t aa = base + OFF_AH + (uint32_t)(((wm*64 + mt*16 + rsel)*PITCH + kofs)*2);
                uint32_t a0,a1,a2,a3;
                LDM4(a0,a1,a2,a3, aa);
#pragma unroll
                for (int nt = 0; nt < 4; nt++){
                    int p = nt >> 1, o = nt & 1;
                    MMA16816(acc[mt][nt], a0,a1,a2,a3, Bh[4*p + 2*o], Bh[4*p + 2*o + 1]);
                }
            }
        }
    }

    // ---------------- epilogue ----------------
    int grp = lane >> 2, tig = lane & 3;
#pragma unroll
    for (int mt = 0; mt < 4; mt++){
        int r0 = m0 + wm*64 + mt*16 + grp;
        int s0r = r0 & (SS-1);
        int s1r = (r0 + 8) & (SS-1);
#pragma unroll
        for (int nt = 0; nt < 4; nt++){
            int c = ncol + wn*32 + nt*8 + tig*2;
            float a0 = acc[mt][nt][0], b0 = acc[mt][nt][1];
            float a1 = acc[mt][nt][2], b1 = acc[mt][nt][3];
            if (MODE == 1){
                *(float2*)&Yext[(size_t)r0*DIM + c]     = make_float2(a0, b0);
                *(float2*)&Yext[(size_t)(r0+8)*DIM + c] = make_float2(a1, b1);
            } else if (widx == 2){
                *(uint32_t*)&g_xvh[(size_t)r0*DIM + c]     = pack2h(a0, b0);
                *(uint32_t*)&g_xvh[(size_t)(r0+8)*DIM + c] = pack2h(a1, b1);
            } else {
                int i = (c & 63) >> 1;
                float c0 = __ldg(&fc[s0r*32 + i]), sn0 = __ldg(&fs[s0r*32 + i]);
                float c1 = __ldg(&fc[s1r*32 + i]), sn1 = __ldg(&fs[s1r*32 + i]);
                float ra0 = a0*c0 - b0*sn0, rb0 = a0*sn0 + b0*c0;
                float ra1 = a1*c1 - b1*sn1, rb1 = a1*sn1 + b1*c1;
                if (widx == 1){
                    *(uint32_t*)&g_kh[(size_t)r0*DIM + c]     = pack2h(ra0, rb0);
                    *(uint32_t*)&g_kh[(size_t)(r0+8)*DIM + c] = pack2h(ra1, rb1);
                } else {
                    *(float2*)&g_xq[(size_t)r0*DIM + c]     = make_float2(a0, b0);
                    *(float2*)&g_xq[(size_t)(r0+8)*DIM + c] = make_float2(a1, b1);
                    *(uint32_t*)&g_qh[(size_t)r0*DIM + c]     = pack2h(ra0*0.125f, rb0*0.125f);
                    *(uint32_t*)&g_qh[(size_t)(r0+8)*DIM + c] = pack2h(ra1*0.125f, rb1*0.125f);
                }
            }
        }
    }
}

__global__ __launch_bounds__(256, 2)
void gemm_qkv(const float* __restrict__ fc, const float* __restrict__ fs)
{ gemm_body<0>(nullptr, fc, fs); }

__global__ __launch_bounds__(256, 2)
void gemm_out(float* __restrict__ out) { gemm_body<1>(out, nullptr, nullptr); }

// ---------------- 4a) init memory buffers ----------------
__global__ __launch_bounds__(256)
void mem_init_kernel(const float* __restrict__ meml_in,
                     const float* __restrict__ memq_in,
                     const float* __restrict__ nrm_in)
{
    int i = blockIdx.x*256 + threadIdx.x;
    g_meml[i] = meml_in[i];
    g_memq[i] = memq_in[i];
    if (i < BB*HH*HD) g_nrmt[i] = nrm_in[i];
}

// ---------------- 4b) memory-branch statistics, chunked over seq ----------------
__global__ __launch_bounds__(256)
void mem_stats_kernel(const float* __restrict__ cache_k,
                      const float* __restrict__ cache_v,
                      const float* __restrict__ pquery)
{
    int bh = blockIdx.x;
    int sc = blockIdx.y;
    int b = bh >> 5, h = bh & 31;
    __shared__ float Ks[32][64];
    __shared__ float Vs[32][64];
    __shared__ float pqs[64];
    __shared__ float sig[32];

    int t = threadIdx.x;
    if (t < 64) pqs[t] = pquery[(b*HH + h)*HD + t];

    float accl[4][4] = {{0}}, accq[4][4] = {{0}};
    float accn = 0.f;
    int lrow = t >> 3;
    int lcol = (t & 7) * 8;
    int d0 = (t >> 4) * 4;
    int e0 = (t & 15) * 4;

    for (int s0 = sc*128; s0 < sc*128 + 128; s0 += 32) {
        __syncthreads();
        const float* kp = cache_k + ((size_t)((b*SS + s0 + lrow)*HH + h))*HD + lcol;
        const float* vp = cache_v + ((size_t)((b*SS + s0 + lrow)*HH + h))*HD + lcol;
        *(float4*)&Ks[lrow][lcol]   = *(const float4*)kp;
        *(float4*)&Ks[lrow][lcol+4] = *(const float4*)(kp + 4);
        *(float4*)&Vs[lrow][lcol]   = *(const float4*)vp;
        *(float4*)&Vs[lrow][lcol+4] = *(const float4*)(vp + 4);
        __syncthreads();
        if (t < 32) {
            float sum = 0.f;
#pragma unroll
            for (int d = 0; d < 64; d++) sum += pqs[d] * Ks[t][d];
            sig[t] = sigmf(sum * 0.125f);
        }
        __syncthreads();
#pragma unroll
        for (int u = 0; u < 8; u++) Ks[lrow][lcol+u] = elu1f(Ks[lrow][lcol+u]);
        __syncthreads();
        if (t < 64) {
#pragma unroll
            for (int s = 0; s < 32; s++) accn += Ks[s][t];
        }
#pragma unroll 4
        for (int s = 0; s < 32; s++) {
            float4 k4 = *(const float4*)&Ks[s][d0];
            float4 v4 = *(const float4*)&Vs[s][e0];
            float sg = sig[s];
            float ka[4] = {k4.x, k4.y, k4.z, k4.w};
            float kb[4] = {k4.x*sg, k4.y*sg, k4.z*sg, k4.w*sg};
            float vv[4] = {v4.x, v4.y, v4.z, v4.w};
#pragma unroll
            for (int i = 0; i < 4; i++)
#pragma unroll
                for (int j = 0; j < 4; j++) {
                    accl[i][j] += ka[i] * vv[j];
                    accq[i][j] += kb[i] * vv[j];
                }
        }
    }
    size_t base = (size_t)bh * HD * HD;
#pragma unroll
    for (int i = 0; i < 4; i++)
#pragma unroll
        for (int j = 0; j < 4; j++) {
            size_t idx = base + (size_t)(d0 + i)*HD + (e0 + j);
            atomicAdd(&g_meml[idx], accl[i][j]);
            atomicAdd(&g_memq[idx], accq[i][j]);
        }
    if (t < 64) atomicAdd(&g_nrmt[bh*HD + t], accn);
}

// ---------------- 5) memory-branch apply -> g_comb ----------------
__global__ __launch_bounds__(256)
void mem_apply_kernel(const float* __restrict__ gmem_w,
                      const float* __restrict__ gmem_b,
                      const float* __restrict__ gate)
{
    int idx = blockIdx.x;
    int st = idx & 31;
    int h  = (idx >> 5) & 31;
    int b  = idx >> 10;
    int bh = b*HH + h;
    int s0 = st * 32;

    __shared__ float ml[64*64];
    __shared__ float mq[64*64];
    __shared__ float sq[32*68];
    __shared__ float nrm[64];
    __shared__ float wv[64];
    __shared__ float gpart[32*8];

    int t = threadIdx.x;
    {
        int r = t >> 2, c = (t & 3) * 16;
        size_t gbase = (size_t)bh*HD*HD + (size_t)r*HD + c;
#pragma unroll
        for (int u = 0; u < 4; u++) {
            *(float4*)&ml[r*64 + c + 4*u] = *(const float4*)&g_meml[gbase + 4*u];
            *(float4*)&mq[r*64 + c + 4*u] = *(const float4*)&g_memq[gbase + 4*u];
        }
    }
    {
        int r = t >> 3, c = (t & 7) * 8;
        const float* xp = g_xq + ((size_t)((b*SS + s0 + r)*HH + h))*HD + c;
        float4 a = *(const float4*)xp;
        float4 bv = *(const float4*)(xp + 4);
        float4 ea = make_float4(elu1f(a.x), elu1f(a.y), elu1f(a.z), elu1f(a.w));
        float4 eb = make_float4(elu1f(bv.x), elu1f(bv.y), elu1f(bv.z), elu1f(bv.w));
        *(float4*)&sq[r*68 + c]     = ea;
        *(float4*)&sq[r*68 + c + 4] = eb;
    }
    if (t < 64) { nrm[t] = g_nrmt[bh*HD + t]; wv[t] = gmem_w[t]; }
    __syncthreads();

    int row = t >> 3;
    int eq  = t & 7;
    float denom = 0.f;
#pragma unroll
    for (int d = 0; d < 64; d++) denom += sq[row*68 + d] * nrm[d];

    float4 mo[2]  = {make_float4(0,0,0,0), make_float4(0,0,0,0)};
    float4 qmo[2] = {make_float4(0,0,0,0), make_float4(0,0,0,0)};
#pragma unroll
    for (int d = 0; d < 64; d++) {
        float sd = sq[row*68 + d];
#pragma unroll
        for (int c = 0; c < 2; c++) {
            float4 m4 = *(const float4*)&ml[d*64 + eq*4 + 32*c];
            float4 q4 = *(const float4*)&mq[d*64 + eq*4 + 32*c];
            mo[c].x += sd*m4.x; mo[c].y += sd*m4.y; mo[c].z += sd*m4.z; mo[c].w += sd*m4.w;
            qmo[c].x += sd*q4.x; qmo[c].y += sd*q4.y; qmo[c].z += sd*q4.z; qmo[c].w += sd*q4.w;
        }
    }
    float inv = 1.f / denom;
    float gp = 0.f;
#pragma unroll
    for (int c = 0; c < 2; c++) {
        mo[c].x *= inv; mo[c].y *= inv; mo[c].z *= inv; mo[c].w *= inv;
        qmo[c].x *= inv; qmo[c].y *= inv; qmo[c].z *= inv; qmo[c].w *= inv;
        int e = eq*4 + 32*c;
        gp += qmo[c].x*wv[e] + qmo[c].y*wv[e+1] + qmo[c].z*wv[e+2] + qmo[c].w*wv[e+3];
    }
    gpart[row*8 + eq] = gp;
    __syncthreads();
    float gsum = 0.f;
#pragma unroll
    for (int i = 0; i < 8; i++) gsum += gpart[row*8 + i];
    float gq = sigmf(gsum + gmem_b[0]);
    float gh = sigmf(gate[h]);

    float* op = g_comb + ((size_t)((b*SS + s0 + row)*HH + h))*HD;
#pragma unroll
    for (int c = 0; c < 2; c++) {
        float4 o;
        o.x = gh * (mo[c].x + gq*qmo[c].x);
        o.y = gh * (mo[c].y + gq*qmo[c].y);
        o.z = gh * (mo[c].z + gq*qmo[c].z);
        o.w = gh * (mo[c].w + gq*qmo[c].w);
        *(float4*)(op + eq*4 + 32*c) = o;
    }
}

// ---------------- 6) transpose V (fp16 in) -> g_vth fp16 ----------------
__global__ __launch_bounds__(256)
void v_trans_kernel()
{
    __shared__ __half sm[64*72];
    int bh = blockIdx.x & 127;
    int st = blockIdx.x >> 7;
    int b = bh >> 5, h = bh & 31;
    int s0 = st * 64;
    int t = threadIdx.x;

    {
        int sl = t >> 2, e0 = (t & 3) * 16;
        const __half* vp = g_xvh + ((size_t)((b*SS + s0 + sl)*HH + h))*HD + e0;
        uint4 v0 = *(const uint4*)vp;
        uint4 v1 = *(const uint4*)(vp + 8);
        *(uint4*)&sm[sl*72 + e0]     = v0;
        *(uint4*)&sm[sl*72 + e0 + 8] = v1;
    }
    __syncthreads();
    {
        int el = t >> 2, sb = (t & 3) * 16;
        __half hv[16];
#pragma unroll
        for (int j = 0; j < 16; j++) hv[j] = sm[(sb + j)*72 + el];
        __half* dst = g_vth + ((size_t)(bh*HD + el))*SS + s0 + sb;
        *(uint4*)dst       = *(uint4*)&hv[0];
        *(uint4*)(dst + 8) = *(uint4*)&hv[8];
    }
}

// ---------------- 7) HMMA flash attention (R14 shape, Q hi-only) ----------
#define PF 72
#define FST0 (64*PF)                 // K/V stages start (halves); Q occupies [0,64*PF)

__device__ __forceinline__ void flash_load_kv(uint32_t skb, int t, int bh, int b, int h, int kt)
{
    int r = t >> 1, c0 = (t & 1) * 32;
    const __half* ks = g_kh + ((size_t)((b*SS + kt*64 + r)*HH + h))*HD + c0;
    const __half* vs = g_vth + ((size_t)(bh*HD + r))*SS + kt*64 + c0;
    uint32_t dk = skb + (uint32_t)((r*PF + c0)*2);
    uint32_t dv = dk + 64*PF*2;
    CP16(dk, ks); CP16(dk+16, ks+8); CP16(dk+32, ks+16); CP16(dk+48, ks+24);
    CP16(dv, vs); CP16(dv+16, vs+8); CP16(dv+32, vs+16); CP16(dv+48, vs+24);
}

__global__ __launch_bounds__(128)
void flash_mma(const float* __restrict__ gate)
{
    extern __shared__ __half fsm[];
    int t = threadIdx.x, lane = t & 31, wid = t >> 5;
    int qt = blockIdx.x & 15;
    int h  = (blockIdx.x >> 4) & 31;
    int b  = blockIdx.x >> 9;
    int bh = b*HH + h;
    uint32_t sb = smem_u32(fsm);

    {
        int r = t >> 1, c0 = (t & 1) * 32;
        const __half* qsh = g_qh + ((size_t)((b*SS + qt*64 + r)*HH + h))*HD + c0;
        uint32_t dh = sb + (uint32_t)((r*PF + c0)*2);
        CP16(dh, qsh); CP16(dh+16, qsh+8); CP16(dh+32, qsh+16); CP16(dh+48, qsh+24);
        CPCOMMIT();
    }
    flash_load_kv(sb + FST0*2, t, bh, b, h, 0);
    CPCOMMIT();

    CPWAIT1();
    __syncthreads();
    int rsel = lane & 15, csel = (lane >> 4) * 8;
    uint32_t qh[4][4];
#pragma unroll
    for (int ks = 0; ks < 4; ks++){
        uint32_t a = sb + (uint32_t)(((wid*16 + rsel)*PF + ks*16 + csel)*2);
        LDM4(qh[ks][0], qh[ks][1], qh[ks][2], qh[ks][3], a);
    }

    float m0 = -1e30f, m1 = -1e30f, l0 = 0.f, l1 = 0.f;
    float O[8][4];
#pragma unroll
    for (int j = 0; j < 8; j++)
#pragma unroll
        for (int r = 0; r < 4; r++) O[j][r] = 0.f;

    int g  = lane >> 2, t2 = lane & 3;

#pragma unroll 1
    for (int kt = 0; kt <= qt; kt++){
        CPWAIT0();
        __syncthreads();
        if (kt < qt){
            flash_load_kv(sb + (FST0 + ((kt+1)&1)*2*64*PF)*2, t, bh, b, h, kt+1);
            CPCOMMIT();
        }
        uint32_t kbase = sb + (uint32_t)((FST0 + (kt&1)*2*64*PF)*2);
        uint32_t vbase = kbase + 64*PF*2;

        float sacc[8][4];
#pragma unroll
        for (int j = 0; j < 8; j++)
#pragma unroll
            for (int r = 0; r < 4; r++) sacc[j][r] = 0.f;
#pragma unroll
        for (int ks = 0; ks < 4; ks++){
#pragma unroll
            for (int nb = 0; nb < 4; nb++){
                uint32_t r0,r1,r2,r3;
                LDM4(r0,r1,r2,r3, kbase + (uint32_t)(((nb*16 + rsel)*PF + ks*16 + csel)*2));
                MMA16816(sacc[2*nb],   qh[ks][0],qh[ks][1],qh[ks][2],qh[ks][3], r0, r2);
                MMA16816(sacc[2*nb+1], qh[ks][0],qh[ks][1],qh[ks][2],qh[ks][3], r1, r3);
            }
        }
        if (kt == qt){
            int ml0 = wid*16 + g, ml1 = ml0 + 8;
#pragma unroll
            for (int j = 0; j < 8; j++){
                int n0 = j*8 + t2*2, n1 = n0 + 1;
                if (n0 > ml0) sacc[j][0] = -1e30f;
                if (n1 > ml0) sacc[j][1] = -1e30f;
                if (n0 > ml1) sacc[j][2] = -1e30f;
                if (n1 > ml1) sacc[j][3] = -1e30f;
            }
        }
        float vx0 = -1e30f, vx1 = -1e30f;
#pragma unroll
        for (int j = 0; j < 8; j++){
            vx0 = fmaxf(vx0, fmaxf(sacc[j][0], sacc[j][1]));
            vx1 = fmaxf(vx1, fmaxf(sacc[j][2], sacc[j][3]));
        }
        vx0 = fmaxf(vx0, __shfl_xor_sync(0xffffffffu, vx0, 1));
        vx0 = fmaxf(vx0, __shfl_xor_sync(0xffffffffu, vx0, 2));
        vx1 = fmaxf(vx1, __shfl_xor_sync(0xffffffffu, vx1, 1));
        vx1 = fmaxf(vx1, __shfl_xor_sync(0xffffffffu, vx1, 2));
        float n0f = fmaxf(m0, vx0), n1f = fmaxf(m1, vx1);
        float c0f = __expf(m0 - n0f), c1f = __expf(m1 - n1f);
        m0 = n0f; m1 = n1f;
        float s0 = 0.f, s1 = 0.f;
#pragma unroll
        for (int j = 0; j < 8; j++){
            sacc[j][0] = __expf(sacc[j][0] - n0f);
            sacc[j][1] = __expf(sacc[j][1] - n0f);
            sacc[j][2] = __expf(sacc[j][2] - n1f);
            sacc[j][3] = __expf(sacc[j][3] - n1f);
            s0 += sacc[j][0] + sacc[j][1];
            s1 += sacc[j][2] + sacc[j][3];
        }
        s0 += __shfl_xor_sync(0xffffffffu, s0, 1);
        s0 += __shfl_xor_sync(0xffffffffu, s0, 2);
        s1 += __shfl_xor_sync(0xffffffffu, s1, 1);
        s1 += __shfl_xor_sync(0xffffffffu, s1, 2);
        l0 = l0*c0f + s0;
        l1 = l1*c1f + s1;
#pragma unroll
        for (int j = 0; j < 8; j++){
            O[j][0] *= c0f; O[j][1] *= c0f;
            O[j][2] *= c1f; O[j][3] *= c1f;
        }
        uint32_t pa[4][4];
#pragma unroll
        for (int ks = 0; ks < 4; ks++){
            pa[ks][0] = pack2h(sacc[2*ks][0],   sacc[2*ks][1]);
            pa[ks][1] = pack2h(sacc[2*ks][2],   sacc[2*ks][3]);
            pa[ks][2] = pack2h(sacc[2*ks+1][0], sacc[2*ks+1][1]);
            pa[ks][3] = pack2h(sacc[2*ks+1][2], sacc[2*ks+1][3]);
        }
#pragma unroll
        for (int ks = 0; ks < 4; ks++){
#pragma unroll
            for (int nb = 0; nb < 4; nb++){
                uint32_t r0,r1,r2,r3;
                LDM4(r0,r1,r2,r3, vbase + (uint32_t)(((nb*16 + rsel)*PF + ks*16 + csel)*2));
                MMA16816(O[2*nb],   pa[ks][0],pa[ks][1],pa[ks][2],pa[ks][3], r0, r2);
                MMA16816(O[2*nb+1], pa[ks][0],pa[ks][1],pa[ks][2],pa[ks][3], r1, r3);
            }
        }
    }

    float gh_ = sigmf(gate[h]);
    float w0 = (1.f - gh_) / l0;
    float w1 = (1.f - gh_) / l1;
    size_t row0 = ((size_t)((b*SS + qt*64 + wid*16 + g)*HH + h))*HD;
    size_t row1 = row0 + (size_t)8*HH*HD;
#pragma unroll
    for (int j = 0; j < 8; j++){
        int c = j*8 + t2*2;
        float2 p0 = *(float2*)&g_comb[row0 + c];
        *(uint32_t*)&g_xhi[row0 + c] = pack2h(p0.x + w0*O[j][0], p0.y + w0*O[j][1]);
        float2 p1 = *(float2*)&g_comb[row1 + c];
        *(uint32_t*)&g_xhi[row1 + c] = pack2h(p1.x + w1*O[j][2], p1.y + w1*O[j][3]);
    }
}

// ---------------- launcher ----------------
extern "C" void kernel_launch(void* const* d_in, const int* in_sizes, int n_in,
                              void* d_out, int out_size)
{
    const float* x     = (const float*)d_in[0];
    const float* pq    = (const float*)d_in[1];
    const float* ck    = (const float*)d_in[2];
    const float* cv    = (const float*)d_in[3];
    const float* meml  = (const float*)d_in[4];
    const float* memq  = (const float*)d_in[5];
    const float* nrm   = (const float*)d_in[6];
    const float* fc    = (const float*)d_in[7];
    const float* fs    = (const float*)d_in[8];
    const float* wq    = (const float*)d_in[10];
    const float* wk    = (const float*)d_in[11];
    const float* wv    = (const float*)d_in[12];
    const float* wo    = (const float*)d_in[13];
    const float* lq1   = (const float*)d_in[14];
    const float* lq2   = (const float*)d_in[15];
    const float* lk1   = (const float*)d_in[16];
    const float* lk2   = (const float*)d_in[17];
    const float* lv1   = (const float*)d_in[18];
    const float* lv2   = (const float*)d_in[19];
    const float* lo1   = (const float*)d_in[20];
    const float* lo2   = (const float*)d_in[21];
    const float* gate  = (const float*)d_in[22];
    const float* gw    = (const float*)d_in[23];
    const float* gb    = (const float*)d_in[24];
    float* out = (float*)d_out;

    static cudaStream_t s2 = nullptr, s3 = nullptr;
    static cudaEvent_t evFork = nullptr, evMem = nullptr, evG = nullptr,
                       evV = nullptr, evW = nullptr;
    if (!s2){
        cudaStreamCreateWithFlags(&s2, cudaStreamNonBlocking);
        cudaStreamCreateWithFlags(&s3, cudaStreamNonBlocking);
        cudaEventCreateWithFlags(&evFork, cudaEventDisableTiming);
        cudaEventCreateWithFlags(&evMem,  cudaEventDisableTiming);
        cudaEventCreateWithFlags(&evG,    cudaEventDisableTiming);
        cudaEventCreateWithFlags(&evV,    cudaEventDisableTiming);
        cudaEventCreateWithFlags(&evW,    cudaEventDisableTiming);
    }

    size_t gsm = NSTG * STG_BYTES;
    cudaFuncSetAttribute(gemm_qkv, cudaFuncAttributeMaxDynamicSharedMemorySize, (int)gsm);
    cudaFuncSetAttribute(gemm_out, cudaFuncAttributeMaxDynamicSharedMemorySize, (int)gsm);
    size_t fsmem = (size_t)(5*64*PF) * sizeof(__half);   // 46080 B
    cudaFuncSetAttribute(flash_mma, cudaFuncAttributeMaxDynamicSharedMemorySize, (int)fsmem);

    cudaEventRecord(evFork, 0);

    // side branch s2: memory-branch statistics (hidden under QKV GEMM)
    cudaStreamWaitEvent(s2, evFork, 0);
    mem_init_kernel<<<(BB*HH*HD*HD)/256, 256, 0, s2>>>(meml, memq, nrm);
    mem_stats_kernel<<<dim3(BB*HH, 8), 256, 0, s2>>>(ck, cv, pq);
    cudaEventRecord(evMem, s2);

    // side branch s3: weight fold runs concurrently with x conversion
    FoldPtrs fp;
    fp.w[0] = wq; fp.w[1] = wk; fp.w[2] = wv; fp.w[3] = wo;
    fp.l1[0] = lq1; fp.l1[1] = lk1; fp.l1[2] = lv1; fp.l1[3] = lo1;
    fp.l2[0] = lq2; fp.l2[1] = lk2; fp.l2[2] = lv2; fp.l2[3] = lo2;
    cudaStreamWaitEvent(s3, evFork, 0);
    fold_split_all<<<dim3(DIM, 4), 256, 0, s3>>>(fp);
    cudaEventRecord(evW, s3);

    // main: x convert + fused QKV GEMM (RoPE epilogue)
    split_x_kernel<<<(MM*DIM)/(256*8), 256>>>(x);
    cudaStreamWaitEvent(0, evW, 0);
    gemm_qkv<<<dim3(3*DIM/128, MM/128), 256, gsm>>>(fc, fs);
    cudaEventRecord(evG, 0);

    // post-GEMM: v_trans on side stream, mem_apply on main
    cudaStreamWaitEvent(s3, evG, 0);
    v_trans_kernel<<<BB*HH*(SS/64), 256, 0, s3>>>();
    cudaEventRecord(evV, s3);

    cudaStreamWaitEvent(0, evMem, 0);
    mem_apply_kernel<<<BB*HH*(SS/32), 256>>>(gw, gb, gate);

    // join, flash, output projection
    cudaStreamWaitEvent(0, evV, 0);
    flash_mma<<<BB*HH*(SS/64), 128, fsmem>>>(gate);
    gemm_out<<<dim3(DIM/128, MM/128), 256, gsm>>>(out);
    (void)in_sizes; (void)n_in; (void)out_size;
}